// round 5
// baseline (speedup 1.0000x reference)
#include <cuda_runtime.h>
#include <math.h>
#include <stdint.h>

#define TOKENS 16384
#define Dm 2048
#define MT 128
#define NCH 64
#define KC 32

// float-index smem offsets
#define XS0 0
#define WS0 4224
#define XS1 8448
#define WS1 12672
#define EMB 0
#define ESTR 132
#define WDT 16896      // 128x128
#define LGF 16896      // logits alias (stride 132), written after GEMM2 done
#define GBT 33792      // g transposed [e][132]
#define ABF 50688      // 16 warps x 128
#define RNNF 52736
#define GAMF 52864
#define BETF 52992
#define SMEM_SZ (53120 * 4)

__device__ float g_WrT[Dm * 128];   // [k][swizzled e-blocks]
__device__ float g_WdT[128 * 128];  // [e][swizzled h-blocks]

typedef unsigned long long ull;

__device__ __forceinline__ void fma2(ull& d, ull a, ull b) {
    asm("fma.rn.f32x2 %0, %1, %2, %0;" : "+l"(d) : "l"(a), "l"(b));
}
__device__ __forceinline__ float2 up2(ull v) {
    float2 r; asm("mov.b64 {%0, %1}, %2;" : "=f"(r.x), "=f"(r.y) : "l"(v)); return r;
}
__device__ __forceinline__ ull pk2(float x, float y) {
    ull r; asm("mov.b64 %0, {%1, %2};" : "=l"(r) : "f"(x), "f"(y)); return r;
}
__device__ __forceinline__ ull swp(ull v) { float2 f = up2(v); return pk2(f.y, f.x); }

__global__ void prep_kernel(const float* __restrict__ Wr, const float* __restrict__ Wd) {
    int i = blockIdx.x * 256 + threadIdx.x;
    {
        int e = i >> 11, k = i & 2047;
        int b = e >> 2, sb = b ^ (b >> 3);
        g_WrT[k * 128 + sb * 4 + (e & 3)] = Wr[i];
    }
    if (i < 128 * 128) {
        int h = i >> 7, e = i & 127;
        int b = h >> 2, sb = b ^ (b >> 3);
        g_WdT[e * 128 + sb * 4 + (h & 3)] = Wd[i];
    }
}

__global__ __launch_bounds__(512, 1) void fused_kernel(
    const float* __restrict__ x, const float* __restrict__ gumbel,
    const float* __restrict__ rnn_g, const float* __restrict__ gamma_g,
    const float* __restrict__ beta_g, const int* __restrict__ topk_p,
    float* __restrict__ out_bin, float* __restrict__ out_ap)
{
    extern __shared__ float fs[];
    const int tid = threadIdx.x;
    const int wid = tid >> 5;
    const int lane = tid & 31;
    const int t0 = blockIdx.x * MT;

    // thread tile: 4 tokens x 8 e(/h)
    const int tm = tid >> 4;          // 0..31
    const int te = tid & 15;          // 0..15
    const int b0 = 2 * te, b1 = 2 * te + 1;
    const int s0 = b0 ^ (b0 >> 3), s1 = b1 ^ (b1 >> 3);

    // ---- stage decoder weights + LN params ----
#pragma unroll
    for (int p = 0; p < 8; p++) {
        int n = tid + 512 * p;
        *(float4*)&fs[WDT + n * 4] = *(const float4*)&g_WdT[n * 4];
    }
    if (tid < 128) {
        fs[RNNF + tid] = rnn_g[tid];
        fs[GAMF + tid] = gamma_g[tid];
        fs[BETF + tid] = beta_g[tid];
    }

    // ---- GEMM1 with double-buffered smem, 1 sync/chunk ----
    float4 xf[2], wf[2];
    const float* xg = x + (size_t)t0 * Dm;

#define LOAD_CHUNK(k0)                                                          \
    {                                                                           \
        _Pragma("unroll")                                                       \
        for (int p = 0; p < 2; p++) {                                           \
            int idx = tid + 512 * p;                                            \
            xf[p] = *(const float4*)&xg[(size_t)(idx >> 3) * Dm + (k0) + (idx & 7) * 4]; \
            wf[p] = *(const float4*)&g_WrT[((k0) + (idx >> 5)) * 128 + (idx & 31) * 4];  \
        }                                                                       \
    }
#define STORE_CHUNK(xdst, wdst)                                                 \
    {                                                                           \
        _Pragma("unroll")                                                       \
        for (int p = 0; p < 2; p++) {                                           \
            int idx = tid + 512 * p;                                            \
            int tok = idx >> 3, kq = (idx & 7) * 4;                             \
            fs[(xdst) + (kq + 0) * 132 + tok] = xf[p].x;                        \
            fs[(xdst) + (kq + 1) * 132 + tok] = xf[p].y;                        \
            fs[(xdst) + (kq + 2) * 132 + tok] = xf[p].z;                        \
            fs[(xdst) + (kq + 3) * 132 + tok] = xf[p].w;                        \
            *(float4*)&fs[(wdst) + (idx >> 5) * 132 + (idx & 31) * 4] = wf[p];  \
        }                                                                       \
    }

    LOAD_CHUNK(0);
    STORE_CHUNK(XS0, WS0);
    LOAD_CHUNK(KC);
    __syncthreads();

    ull P[2][4], Q[2][4];
#pragma unroll
    for (int i = 0; i < 2; i++)
#pragma unroll
        for (int j = 0; j < 4; j++) { P[i][j] = 0ull; Q[i][j] = 0ull; }

    for (int ch = 0; ch < NCH; ++ch) {
        const int cur = ch & 1;
        if (ch + 1 < NCH) {
            if (cur) STORE_CHUNK(XS0, WS0) else STORE_CHUNK(XS1, WS1);
        }
        if (ch + 2 < NCH) LOAD_CHUNK((ch + 2) * KC);

        const int xb = (cur ? XS1 : XS0) + 4 * tm;
        const int w0 = (cur ? WS1 : WS0) + 4 * s0;
        const int w1 = (cur ? WS1 : WS0) + 4 * s1;
#pragma unroll 8
        for (int k = 0; k < KC; ++k) {
            ulonglong2 a = *(const ulonglong2*)&fs[xb + k * 132];
            ull as0 = swp(a.x), as1 = swp(a.y);
            ulonglong2 Bx = *(const ulonglong2*)&fs[w0 + k * 132];
            ulonglong2 By = *(const ulonglong2*)&fs[w1 + k * 132];
            ull b[4] = {Bx.x, Bx.y, By.x, By.y};
#pragma unroll
            for (int j = 0; j < 4; j++) {
                fma2(P[0][j], a.x, b[j]);
                fma2(Q[0][j], as0, b[j]);
                fma2(P[1][j], a.y, b[j]);
                fma2(Q[1][j], as1, b[j]);
            }
        }
        __syncthreads();
    }

    // unpack emb (aliases GEMM buffers)
#pragma unroll
    for (int i = 0; i < 2; i++)
#pragma unroll
        for (int j = 0; j < 4; j++) {
            float2 p = up2(P[i][j]), q = up2(Q[i][j]);
            int r0 = 4 * tm + 2 * i, c0 = 8 * te + 2 * j;
            *(float2*)&fs[EMB + r0 * ESTR + c0]       = make_float2(p.x, q.y);
            *(float2*)&fs[EMB + (r0 + 1) * ESTR + c0] = make_float2(q.x, p.y);
        }
    __syncthreads();

    // ---- LN + GELU, write transposed g[e][tok] ----
    for (int tt = 0; tt < 8; ++tt) {
        const int t = wid * 8 + tt;
        float v[4];
#pragma unroll
        for (int j = 0; j < 4; j++) {
            int e = lane + 32 * j;
            v[j] = fs[EMB + t * ESTR + e] + fs[RNNF + e];
        }
        float s = v[0] + v[1] + v[2] + v[3];
#pragma unroll
        for (int o = 16; o > 0; o >>= 1) s += __shfl_xor_sync(0xffffffffu, s, o);
        const float mu = s * (1.0f / 128.0f);
        float q = 0.f;
#pragma unroll
        for (int j = 0; j < 4; j++) { float d = v[j] - mu; q += d * d; }
#pragma unroll
        for (int o = 16; o > 0; o >>= 1) q += __shfl_xor_sync(0xffffffffu, q, o);
        const float inv = rsqrtf(q * (1.0f / 128.0f) + 1e-5f);
#pragma unroll
        for (int j = 0; j < 4; j++) {
            int e = lane + 32 * j;
            float h = (v[j] - mu) * inv * fs[GAMF + e] + fs[BETF + e];
            fs[GBT + e * 132 + t] = 0.5f * h * (1.0f + erff(h * 0.70710678118654752f));
        }
    }
    __syncthreads();

    // ---- GEMM2 (tiled): logits[t][h] = sum_e g[t][e] * WdT[e][h] ----
    {
        ull P2[2][4], Q2[2][4];
#pragma unroll
        for (int i = 0; i < 2; i++)
#pragma unroll
            for (int j = 0; j < 4; j++) { P2[i][j] = 0ull; Q2[i][j] = 0ull; }

        const int gp = GBT + 4 * tm;
        const int v0 = WDT + 4 * s0;
        const int v1 = WDT + 4 * s1;
#pragma unroll 8
        for (int e = 0; e < 128; ++e) {
            ulonglong2 a = *(const ulonglong2*)&fs[gp + e * 132];
            ull as0 = swp(a.x), as1 = swp(a.y);
            ulonglong2 Bx = *(const ulonglong2*)&fs[v0 + e * 128];
            ulonglong2 By = *(const ulonglong2*)&fs[v1 + e * 128];
            ull b[4] = {Bx.x, Bx.y, By.x, By.y};
#pragma unroll
            for (int j = 0; j < 4; j++) {
                fma2(P2[0][j], a.x, b[j]);
                fma2(Q2[0][j], as0, b[j]);
                fma2(P2[1][j], a.y, b[j]);
                fma2(Q2[1][j], as1, b[j]);
            }
        }
        __syncthreads();   // done reading WDT; logits alias it
#pragma unroll
        for (int i = 0; i < 2; i++)
#pragma unroll
            for (int j = 0; j < 4; j++) {
                float2 p = up2(P2[i][j]), q = up2(Q2[i][j]);
                int r0 = 4 * tm + 2 * i, c0 = 8 * te + 2 * j;
                *(float2*)&fs[LGF + r0 * 132 + c0]       = make_float2(p.x, q.y);
                *(float2*)&fs[LGF + (r0 + 1) * 132 + c0] = make_float2(q.x, p.y);
            }
    }
    __syncthreads();

    // ---- gumbel-sigmoid + round + top-k mask ----
    const int K = *topk_p;
    const float Kf = (float)K;

    for (int tt = 0; tt < 8; ++tt) {
        const int t = wid * 8 + tt;
        const int gt = t0 + t;

        float4 lgv = *(const float4*)&fs[LGF + t * 132 + lane * 4];
        float lg[4] = {lgv.x, lgv.y, lgv.z, lgv.w};
        float4 gu = *(const float4*)&gumbel[(size_t)gt * 128 + lane * 4];
        float gua[4] = {gu.x, gu.y, gu.z, gu.w};

        float ap[4], bn[4];
        float csum = 0.f;
#pragma unroll
        for (int jj = 0; jj < 4; jj++) {
            float z = (lg[jj] + gua[jj] + 3.0f) * 2.5f;
            ap[jj] = 1.0f / (1.0f + expf(-z));
            bn[jj] = rintf(ap[jj]);
            csum += bn[jj];
        }
#pragma unroll
        for (int o = 16; o > 0; o >>= 1) csum += __shfl_xor_sync(0xffffffffu, csum, o);

        float ob[4];
        if (csum > Kf || csum == 0.0f) {
            const int kneed = (csum > Kf) ? K : 1;
#pragma unroll
            for (int jj = 0; jj < 4; jj++) fs[ABF + wid * 128 + lane * 4 + jj] = ap[jj];
            __syncwarp();
            int r[4] = {0, 0, 0, 0};
            for (int j4 = 0; j4 < 128; j4 += 4) {
                float4 av = *(const float4*)&fs[ABF + wid * 128 + j4];
                float aj[4] = {av.x, av.y, av.z, av.w};
#pragma unroll
                for (int u = 0; u < 4; u++) {
                    int j = j4 + u;
#pragma unroll
                    for (int jj = 0; jj < 4; jj++) {
                        int idx = lane * 4 + jj;
                        r[jj] += (aj[u] > ap[jj]) || (aj[u] == ap[jj] && j < idx);
                    }
                }
            }
#pragma unroll
            for (int jj = 0; jj < 4; jj++) ob[jj] = (r[jj] < kneed) ? 1.0f : 0.0f;
            __syncwarp();
        } else {
#pragma unroll
            for (int jj = 0; jj < 4; jj++) ob[jj] = bn[jj];
        }

        *(float4*)&out_bin[(size_t)gt * 128 + lane * 4] = make_float4(ob[0], ob[1], ob[2], ob[3]);
        if (out_ap)
            *(float4*)&out_ap[(size_t)gt * 128 + lane * 4] = make_float4(ap[0], ap[1], ap[2], ap[3]);
    }
}

extern "C" void kernel_launch(void* const* d_in, const int* in_sizes, int n_in,
                              void* d_out, int out_size) {
    const float* x        = (const float*)d_in[0];
    const float* W_router = (const float*)d_in[1];
    const float* W_dec    = (const float*)d_in[2];
    const float* ln_gamma = (const float*)d_in[3];
    const float* ln_beta  = (const float*)d_in[4];
    const float* rnn      = (const float*)d_in[5];
    const float* gumbel   = (const float*)d_in[6];
    const int*   topk     = (const int*)d_in[7];

    float* out_bin = (float*)d_out;
    const size_t N = (size_t)TOKENS * 128;
    float* out_ap = ((size_t)out_size >= 2 * N) ? out_bin + N : nullptr;

    prep_kernel<<<(128 * Dm) / 256, 256>>>(W_router, W_dec);

    cudaFuncSetAttribute(fused_kernel, cudaFuncAttributeMaxDynamicSharedMemorySize, SMEM_SZ);
    fused_kernel<<<TOKENS / MT, 512, SMEM_SZ>>>(
        x, gumbel, rnn, ln_gamma, ln_beta, topk, out_bin, out_ap);
}